// round 2
// baseline (speedup 1.0000x reference)
#include <cuda_runtime.h>
#include <stdint.h>

// ---------------------------------------------------------------------------
// Problem constants
// ---------------------------------------------------------------------------
#define Gc 64
#define Nc 256
#define Fc 20
#define Hc 32
#define Kc 5
#define NSc 100

// JAX RNG mode: 1 = threefry_partitionable (modern default), 0 = legacy.
#define JAX_PARTITIONABLE 1

static const size_t PROB_ELEMS = (size_t)Gc * Nc * Nc * Kc;            // 20971520
static const size_t LA_OFF     = PROB_ELEMS;                           // 20971520
static const size_t ZMU_OFF    = LA_OFF + (size_t)Gc * Kc;             // 20971840
static const size_t LOSS_OFF   = ZMU_OFF + (size_t)Gc * Nc * Hc;       // 21496128

// ---------------------------------------------------------------------------
// Scratch (device globals; no runtime allocation allowed)
// ---------------------------------------------------------------------------
__device__ float g_ha[(size_t)Gc * Nc * Hc];              // 2 MB
__device__ float g_thresh[(size_t)Kc * Gc * Nc * Nc];     // 84 MB  sigmoid(-theta) [k][g][i][j]
__device__ float g_la[Gc * Kc];
__device__ float g_partial[NSc * Gc];

// ---------------------------------------------------------------------------
// threefry2x32 (bit-exact JAX)
// ---------------------------------------------------------------------------
struct U2 { unsigned int x, y; };

__device__ __forceinline__ unsigned int rotl32(unsigned int v, int r) {
    return (v << r) | (v >> (32 - r));
}

__device__ __forceinline__ U2 threefry(unsigned int k0, unsigned int k1,
                                       unsigned int x0, unsigned int x1)
{
    unsigned int k2 = k0 ^ k1 ^ 0x1BD11BDAu;
    x0 += k0; x1 += k1;
#define TFR(r) { x0 += x1; x1 = rotl32(x1, r) ^ x0; }
    TFR(13) TFR(15) TFR(26) TFR(6)
    x0 += k1; x1 += k2 + 1u;
    TFR(17) TFR(29) TFR(16) TFR(24)
    x0 += k2; x1 += k0 + 2u;
    TFR(13) TFR(15) TFR(26) TFR(6)
    x0 += k0; x1 += k1 + 3u;
    TFR(17) TFR(29) TFR(16) TFR(24)
    x0 += k1; x1 += k2 + 4u;
    TFR(13) TFR(15) TFR(26) TFR(6)
    x0 += k2; x1 += k0 + 5u;
#undef TFR
    U2 r; r.x = x0; r.y = x1; return r;
}

// 32-bit random bits for element index idx (partitionable scheme):
// bits[i] = x ^ y of threefry(key, (hi32(i)=0, lo32(i)))
__device__ __forceinline__ unsigned int rbits(unsigned int k0, unsigned int k1,
                                              unsigned int idx)
{
#if JAX_PARTITIONABLE
    U2 r = threefry(k0, k1, 0u, idx);
    return r.x ^ r.y;
#else
    // legacy: handled per-callsite in partitionable build; placeholder
    U2 r = threefry(k0, k1, 0u, idx);
    return r.x;
#endif
}

__device__ __forceinline__ float bits_to_f01(unsigned int b)
{
    return __uint_as_float((b >> 9) | 0x3f800000u) - 1.0f;
}

// XLA fp32 ErfInv (Giles polynomial) — matches lax.erf_inv
__device__ __forceinline__ float erfinv32(float x)
{
    float w = -log1pf(-x * x);
    float p;
    if (w < 5.0f) {
        w = w - 2.5f;
        p = 2.81022636e-08f;
        p = fmaf(p, w, 3.43273939e-07f);
        p = fmaf(p, w, -3.5233877e-06f);
        p = fmaf(p, w, -4.39150654e-06f);
        p = fmaf(p, w, 0.00021858087f);
        p = fmaf(p, w, -0.00125372503f);
        p = fmaf(p, w, -0.00417768164f);
        p = fmaf(p, w, 0.246640727f);
        p = fmaf(p, w, 1.50140941f);
    } else {
        w = sqrtf(w) - 3.0f;
        p = -0.000200214257f;
        p = fmaf(p, w, 0.000100950558f);
        p = fmaf(p, w, 0.00134934322f);
        p = fmaf(p, w, -0.00367342844f);
        p = fmaf(p, w, 0.00573950773f);
        p = fmaf(p, w, -0.0076224613f);
        p = fmaf(p, w, 0.00943887047f);
        p = fmaf(p, w, 1.00167406f);
        p = fmaf(p, w, 2.83297682f);
    }
    return p * x;
}

// ---------------------------------------------------------------------------
// Encoders: Z_mu and ha
// ---------------------------------------------------------------------------
__global__ void encode_kernel(const float* __restrict__ X,
                              const float* __restrict__ Wz1, const float* __restrict__ bz1,
                              const float* __restrict__ Wz2, const float* __restrict__ bz2,
                              const float* __restrict__ Wa1, const float* __restrict__ ba1,
                              float* __restrict__ zmu_out)
{
    __shared__ float sWz1[Fc * Hc], sbz1[Hc], sWz2[Hc * Hc], sbz2[Hc];
    __shared__ float sWa1[Fc * Hc], sba1[Hc];
    int t = threadIdx.x, g = blockIdx.x;
    for (int i = t; i < Fc * Hc; i += 256) { sWz1[i] = Wz1[i]; sWa1[i] = Wa1[i]; }
    for (int i = t; i < Hc * Hc; i += 256) sWz2[i] = Wz2[i];
    if (t < Hc) { sbz1[t] = bz1[t]; sbz2[t] = bz2[t]; sba1[t] = ba1[t]; }
    __syncthreads();

    float xr[Fc];
    const float* xp = X + ((size_t)g * Nc + t) * Fc;
#pragma unroll
    for (int f = 0; f < Fc; ++f) xr[f] = xp[f];

    float hz[Hc];
#pragma unroll
    for (int h = 0; h < Hc; ++h) {
        float a = sbz1[h];
#pragma unroll
        for (int f = 0; f < Fc; ++f) a = fmaf(xr[f], sWz1[f * Hc + h], a);
        hz[h] = fmaxf(a, 0.0f);
    }
    float* zo = zmu_out + ((size_t)g * Nc + t) * Hc;
#pragma unroll
    for (int h = 0; h < Hc; ++h) {
        float a = sbz2[h];
#pragma unroll
        for (int q = 0; q < Hc; ++q) a = fmaf(hz[q], sWz2[q * Hc + h], a);
        zo[h] = a;
    }
    float* hao = g_ha + ((size_t)g * Nc + t) * Hc;
#pragma unroll
    for (int h = 0; h < Hc; ++h) {
        float a = sba1[h];
#pragma unroll
        for (int f = 0; f < Fc; ++f) a = fmaf(xr[f], sWa1[f * Hc + h], a);
        hao[h] = fmaxf(a, 0.0f);
    }
}

// ---------------------------------------------------------------------------
// logit_alpha
// ---------------------------------------------------------------------------
__global__ void alpha_kernel(const float* __restrict__ Walpha,
                             const float* __restrict__ balpha,
                             float* __restrict__ la_out)
{
    __shared__ float red[256];
    int g = blockIdx.x, t = threadIdx.x;
    int h = t & 31, grp = t >> 5;
    float s = 0.0f;
    for (int n = grp; n < Nc; n += 8) s += g_ha[((size_t)g * Nc + n) * Hc + h];
    red[t] = s;
    __syncthreads();
    if (grp == 0) {
        float m = red[h] + red[32 + h] + red[64 + h] + red[96 + h] +
                  red[128 + h] + red[160 + h] + red[192 + h] + red[224 + h];
        red[h] = m * (1.0f / (float)Nc);
    }
    __syncthreads();
    if (t < Kc) {
        float a = balpha[t];
#pragma unroll
        for (int hh = 0; hh < Hc; ++hh) a = fmaf(red[hh], Walpha[hh * Kc + t], a);
        la_out[g * Kc + t] = a;
        g_la[g * Kc + t] = a;
    }
}

// ---------------------------------------------------------------------------
// theta: prob_theta (output) + thresh = sigmoid(-logit) (scratch)
// dynamic smem: ha[256*33] + B[256*33] + Th[32*32] = 17920 floats = 71680 B
// ---------------------------------------------------------------------------
__global__ void theta_kernel(const float* __restrict__ Wtheta,
                             float* __restrict__ prob_out)
{
    extern __shared__ float sm[];
    float* ha = sm;
    float* B  = sm + Nc * 33;
    float* Th = sm + 2 * Nc * 33;
    int bid = blockIdx.x;
    int g = bid / Kc, k = bid % Kc;
    int t = threadIdx.x;

    for (int e = t; e < Nc * Hc; e += 256) {
        int i = e >> 5, h = e & 31;
        ha[i * 33 + h] = g_ha[((size_t)g * Nc + i) * Hc + h];
    }
    for (int e = t; e < Hc * Hc; e += 256) Th[e] = Wtheta[(size_t)e * Kc + k];
    __syncthreads();

    for (int e = t; e < Nc * Hc; e += 256) {
        int i = e >> 5, f = e & 31;
        float a = 0.0f;
#pragma unroll
        for (int h = 0; h < Hc; ++h) a = fmaf(ha[i * 33 + h], Th[h * Hc + f], a);
        B[i * 33 + f] = a;
    }
    __syncthreads();

    int lane = t & 31, w = t >> 5;
    for (int ii = 0; ii < 32; ++ii) {
        int i = w * 32 + ii;
        float br[Hc];
#pragma unroll
        for (int f = 0; f < Hc; ++f) br[f] = B[i * 33 + f];
        for (int jh = 0; jh < 8; ++jh) {
            int j = jh * 32 + lane;
            float a = 0.0f;
#pragma unroll
            for (int f = 0; f < Hc; ++f) a = fmaf(br[f], ha[j * 33 + f], a);
            float prob = 1.0f / (1.0f + expf(-a));
            float th   = 1.0f / (1.0f + expf(a));
            prob_out[(((size_t)g * Nc + i) * Nc + j) * Kc + k] = (i == j) ? 0.0f : prob;
            g_thresh[(((size_t)k * Gc + g) * Nc + i) * Nc + j] = th;
        }
    }
}

// ---------------------------------------------------------------------------
// A-mult: Out = A @ In, A = smem bitmask, pitch-33 buffers
// ---------------------------------------------------------------------------
__device__ __forceinline__ void amul(const float* __restrict__ In,
                                     float* __restrict__ Out,
                                     const unsigned int* __restrict__ Ab, int t)
{
    int lane = t & 31, w = t >> 5;
    for (int grp = w; grp < 32; grp += 8) {
        int r0 = grp << 3;
        float a0 = 0.f, a1 = 0.f, a2 = 0.f, a3 = 0.f;
        float a4 = 0.f, a5 = 0.f, a6 = 0.f, a7 = 0.f;
        for (int wd = 0; wd < 8; ++wd) {
            unsigned int m0 = Ab[(r0 + 0) * 8 + wd];
            unsigned int m1 = Ab[(r0 + 1) * 8 + wd];
            unsigned int m2 = Ab[(r0 + 2) * 8 + wd];
            unsigned int m3 = Ab[(r0 + 3) * 8 + wd];
            unsigned int m4 = Ab[(r0 + 4) * 8 + wd];
            unsigned int m5 = Ab[(r0 + 5) * 8 + wd];
            unsigned int m6 = Ab[(r0 + 6) * 8 + wd];
            unsigned int m7 = Ab[(r0 + 7) * 8 + wd];
            const float* zp = In + (wd * 32) * 33 + lane;
#pragma unroll
            for (int b = 0; b < 32; ++b) {
                float zv = zp[b * 33];
                unsigned int msk = 1u << b;
                if (m0 & msk) a0 += zv;
                if (m1 & msk) a1 += zv;
                if (m2 & msk) a2 += zv;
                if (m3 & msk) a3 += zv;
                if (m4 & msk) a4 += zv;
                if (m5 & msk) a5 += zv;
                if (m6 & msk) a6 += zv;
                if (m7 & msk) a7 += zv;
            }
        }
        Out[(r0 + 0) * 33 + lane] = a0;
        Out[(r0 + 1) * 33 + lane] = a1;
        Out[(r0 + 2) * 33 + lane] = a2;
        Out[(r0 + 3) * 33 + lane] = a3;
        Out[(r0 + 4) * 33 + lane] = a4;
        Out[(r0 + 5) * 33 + lane] = a5;
        Out[(r0 + 6) * 33 + lane] = a6;
        Out[(r0 + 7) * 33 + lane] = a7;
    }
}

// ---------------------------------------------------------------------------
// Fused per-(sample, graph) kernel
// dynamic smem: 20928 floats = 83712 bytes
// ---------------------------------------------------------------------------
__global__ void __launch_bounds__(256)
sample_kernel(const float* __restrict__ zmu,
              const float* __restrict__ Wd1, const float* __restrict__ bd1,
              const float* __restrict__ Wd2, const float* __restrict__ bd2,
              const float* __restrict__ X, const int* __restrict__ seedp)
{
    extern __shared__ float sm[];
    float* Zs   = sm;                    // 8448
    float* Tb   = sm + 8448;             // 8448
    float* sWd1 = sm + 16896;            // 1024
    float* sbd1 = sm + 17920;            // 32
    float* sWd2 = sm + 17952;            // 640
    float* sbd2 = sm + 18592;            // 32 (20 used)
    float* red  = sm + 18624;            // 256
    unsigned int* Ab = (unsigned int*)(sm + 18880); // 2048 words
    __shared__ unsigned int sk[4];
    __shared__ int skg;

    const int t = threadIdx.x;
    const int bid = blockIdx.x;
    const int g  = bid & (Gc - 1);
    const int si = bid >> 6;

    for (int e = t; e < Hc * Hc; e += 256) sWd1[e] = Wd1[e];
    for (int e = t; e < Hc * Fc; e += 256) sWd2[e] = Wd2[e];
    if (t < Hc) sbd1[t] = bd1[t];
    if (t < Fc) sbd2[t] = bd2[t];
    for (int e = t; e < Nc * 8; e += 256) Ab[e] = 0u;

    if (t == 0) {
        unsigned int seed = (unsigned int)(*seedp);
        // base = key(seed) = (0, seed); fold_in(base, si) = threefry(base, (0, si))
        U2 kf = threefry(0u, seed, 0u, (unsigned int)si);
#if JAX_PARTITIONABLE
        // split(kf, 3)[i] = threefry(kf, (0, i))
        U2 k1 = threefry(kf.x, kf.y, 0u, 0u);
        U2 k2 = threefry(kf.x, kf.y, 0u, 1u);
        U2 k3 = threefry(kf.x, kf.y, 0u, 2u);
#else
        // legacy split: threefry over iota(6) halves, (3,2) reshape
        U2 l0 = threefry(kf.x, kf.y, 0u, 3u);
        U2 l1 = threefry(kf.x, kf.y, 1u, 4u);
        U2 l2 = threefry(kf.x, kf.y, 2u, 5u);
        U2 k1; k1.x = l0.x; k1.y = l1.x;
        U2 k2; k2.x = l2.x; k2.y = l0.y;
        U2 k3; k3.x = l1.y; k3.y = l2.y;
#endif
        sk[0] = k1.x; sk[1] = k1.y; sk[2] = k3.x; sk[3] = k3.y;

        // gumbel-softmax hard argmax over K components
        const float tinyf = 1.17549435e-38f;
        float best = -1e30f; int kg = 0;
#pragma unroll
        for (int k = 0; k < Kc; ++k) {
            unsigned int b = rbits(k2.x, k2.y, (unsigned int)(g * Kc + k));
            float f = bits_to_f01(b);
            float u = fmaxf(f, tinyf);          // == f*(1-tiny)+tiny then max(tiny,.)
            float gv = -logf(-logf(u));
            float sc = g_la[g * Kc + k] + gv;   // argmax-equivalent to softmax((la+g)/tau)
            if (sc > best) { best = sc; kg = k; }
        }
        skg = kg;
    }
    __syncthreads();

    const unsigned int k1x = sk[0], k1y = sk[1], k3x = sk[2], k3y = sk[3];
    const int ksel = skg;
    const float stdv = expf(-1.5f);

    // ---- sample Z = Z_mu + std * normal ----
    for (int l = t; l < Nc * Hc; l += 256) {
        unsigned int b = rbits(k1x, k1y, (unsigned int)(g * (Nc * Hc) + l));
        float f = bits_to_f01(b);
        float u = __fadd_rn(__fmul_rn(f, 2.0f), -0.99999994f);
        u = fmaxf(-0.99999994f, u);
        float nv = 1.41421356f * erfinv32(u);
        int n = l >> 5, h = l & 31;
        Zs[n * 33 + h] = zmu[((size_t)g * Nc + n) * Hc + h] + stdv * nv;
    }

    // ---- sample adjacency (strict lower triangle), build symmetric bitmask ----
    {
        const float* thr = g_thresh + ((size_t)ksel * Gc + g) * (Nc * Nc);
        const float loA = 1e-6f;
        const float scA = (1.0f - 1e-6f) - 1e-6f;
        for (int c = t; c < 32640; c += 256) {
            int pr = c / 255;
            int o  = c - pr * 255;
            int i, j;
            if (o < pr) { i = pr; j = o; }
            else        { i = 255 - pr; j = o - pr; }
            unsigned int b = rbits(k3x, k3y, (unsigned int)(g * (Nc * Nc) + i * Nc + j));
            float f = bits_to_f01(b);
            float u = __fadd_rn(__fmul_rn(f, scA), loA);
            u = fmaxf(loA, u);
            if (u > thr[i * Nc + j]) {
                atomicOr(&Ab[i * 8 + (j >> 5)], 1u << (j & 31));
                atomicOr(&Ab[j * 8 + (i >> 5)], 1u << (i & 31));
            }
        }
    }
    __syncthreads();

    // ---- T1 = A @ Z ----
    amul(Zs, Tb, Ab, t);
    __syncthreads();

    // ---- h = relu(T1 @ Wd1 + bd1) (row t per thread) ----
    {
        float tr[Hc];
#pragma unroll
        for (int f2 = 0; f2 < Hc; ++f2) tr[f2] = Tb[t * 33 + f2];
#pragma unroll
        for (int h = 0; h < Hc; ++h) {
            float a = sbd1[h];
#pragma unroll
            for (int f2 = 0; f2 < Hc; ++f2) a = fmaf(tr[f2], sWd1[f2 * Hc + h], a);
            Zs[t * 33 + h] = fmaxf(a, 0.0f);
        }
    }
    __syncthreads();

    // ---- T2 = A @ h ----
    amul(Zs, Tb, Ab, t);
    __syncthreads();

    // ---- Xmu = T2 @ Wd2 + bd2 ; accumulate squared error ----
    float local = 0.0f;
    {
        float t2[Hc];
#pragma unroll
        for (int h = 0; h < Hc; ++h) t2[h] = Tb[t * 33 + h];
        const float* xr = X + ((size_t)g * Nc + t) * Fc;
#pragma unroll
        for (int f2 = 0; f2 < Fc; ++f2) {
            float a = sbd2[f2];
#pragma unroll
            for (int h = 0; h < Hc; ++h) a = fmaf(t2[h], sWd2[h * Fc + f2], a);
            float d = a - xr[f2];
            local = fmaf(d, d, local);
        }
    }
    red[t] = local;
    __syncthreads();
    for (int s = 128; s > 0; s >>= 1) {
        if (t < s) red[t] += red[t + s];
        __syncthreads();
    }
    if (t == 0) g_partial[bid] = red[0];
}

// ---------------------------------------------------------------------------
// Final loss reduction
// ---------------------------------------------------------------------------
__global__ void finalize_kernel(float* __restrict__ out)
{
    __shared__ double rd[256];
    int t = threadIdx.x;
    double s = 0.0;
    for (int i = t; i < NSc * Gc; i += 256) s += (double)g_partial[i];
    rd[t] = s;
    __syncthreads();
    for (int k = 128; k > 0; k >>= 1) {
        if (t < k) rd[t] += rd[t + k];
        __syncthreads();
    }
    if (t == 0) out[LOSS_OFF] = (float)(rd[0] * (0.5 / (double)(Gc * NSc)));
}

// ---------------------------------------------------------------------------
// Launch
// ---------------------------------------------------------------------------
extern "C" void kernel_launch(void* const* d_in, const int* in_sizes, int n_in,
                              void* d_out, int out_size)
{
    (void)in_sizes; (void)n_in; (void)out_size;
    const float* X      = (const float*)d_in[0];
    const float* Wz1    = (const float*)d_in[1];
    const float* bz1    = (const float*)d_in[2];
    const float* Wz2    = (const float*)d_in[3];
    const float* bz2    = (const float*)d_in[4];
    const float* Wa1    = (const float*)d_in[5];
    const float* ba1    = (const float*)d_in[6];
    const float* Wtheta = (const float*)d_in[7];
    const float* Walpha = (const float*)d_in[8];
    const float* balpha = (const float*)d_in[9];
    const float* Wd1    = (const float*)d_in[10];
    const float* bd1    = (const float*)d_in[11];
    const float* Wd2    = (const float*)d_in[12];
    const float* bd2    = (const float*)d_in[13];
    const int*   seed   = (const int*)d_in[14];

    float* out  = (float*)d_out;
    float* prob = out;
    float* la   = out + LA_OFF;
    float* zmu  = out + ZMU_OFF;

    cudaFuncSetAttribute(theta_kernel,  cudaFuncAttributeMaxDynamicSharedMemorySize, 71680);
    cudaFuncSetAttribute(sample_kernel, cudaFuncAttributeMaxDynamicSharedMemorySize, 83712);

    encode_kernel<<<Gc, 256>>>(X, Wz1, bz1, Wz2, bz2, Wa1, ba1, zmu);
    alpha_kernel<<<Gc, 256>>>(Walpha, balpha, la);
    theta_kernel<<<Gc * Kc, 256, 71680>>>(Wtheta, prob);
    sample_kernel<<<NSc * Gc, 256, 83712>>>(zmu, Wd1, bd1, Wd2, bd2, X, seed);
    finalize_kernel<<<1, 256>>>(out);
}